// round 10
// baseline (speedup 1.0000x reference)
#include <cuda_runtime.h>

#define MAXN 50000
#define MAXE 1600000
#define DD 64
#define NPW 4   // nodes per warp in k_node

__device__ __align__(16) float g_P[MAXN * DD];     // feat @ W_rel
__device__ __align__(16) float g_L[MAXN * DD];     // feat @ (loop or evolve)
__device__ float g_ssrc[MAXN];
__device__ float g_sdst[MAXN];
__device__ int   g_cnt[MAXN];                      // in-degree
__device__ int   g_off[MAXN];                      // exclusive prefix of cnt
__device__ int   g_cur[MAXN];                      // scatter cursor
__device__ int   g_psrc[MAXE];                     // src permuted by dst
__device__ float g_patt[MAXE];                     // att permuted by dst

// packed f32x2 FMA: acc = a*b + acc (both lanes)
__device__ __forceinline__ void ffma2(unsigned long long& acc,
                                      unsigned long long a,
                                      unsigned long long b) {
    asm("fma.rn.f32x2 %0, %1, %2, %0;" : "+l"(acc) : "l"(a), "l"(b));
}
__device__ __forceinline__ unsigned long long pack2(float v) {
    unsigned long long r;
    unsigned int u = __float_as_uint(v);
    asm("mov.b64 %0, {%1, %1};" : "=l"(r) : "r"(u));
    return r;
}

__device__ __forceinline__ float sigrelu(float x) {
    return (x > 0.f) ? __fdividef(1.f, 1.f + __expf(-x)) : 0.5f;
}

// ---------------------------------------------------------------------------
// Kernel 0: zero the degree histogram
// ---------------------------------------------------------------------------
__global__ void k_zero(int N) {
    int i = blockIdx.x * blockDim.x + threadIdx.x;
    if (i < N) g_cnt[i] = 0;
}

// ---------------------------------------------------------------------------
// Kernel 1: in-degree histogram (4 edges/thread, int4)
// ---------------------------------------------------------------------------
__global__ void k_hist(const int* __restrict__ dst, int E) {
    int i = blockIdx.x * blockDim.x + threadIdx.x;
    int e = i * 4;
    if (e + 3 < E) {
        int4 d = *(const int4*)(dst + e);
        atomicAdd(&g_cnt[d.x], 1);
        atomicAdd(&g_cnt[d.y], 1);
        atomicAdd(&g_cnt[d.z], 1);
        atomicAdd(&g_cnt[d.w], 1);
    } else {
        for (int k = e; k < E; k++) atomicAdd(&g_cnt[dst[k]], 1);
    }
}

// ---------------------------------------------------------------------------
// Kernel 2: node precompute, persistent grid, 4 nodes/warp, packed f32x2 FMA.
//   P = feat@W_rel ; L = feat@(cnt>0 ? loop : evolve) ; ssrc/sdst scalars
// ---------------------------------------------------------------------------
__global__ void k_node(const float* __restrict__ feat,
                       const float* __restrict__ W_rel,
                       const float* __restrict__ lin_w,
                       const float* __restrict__ loop_w,
                       const float* __restrict__ evolve_w,
                       int N) {
    __shared__ float2 sW[2048];
    __shared__ float2 sLp[2048];
    __shared__ float2 sEv[2048];
    int tid = threadIdx.x;
    for (int idx = tid; idx < 2048; idx += blockDim.x) {
        int k = idx >> 5, j = idx & 31;
        sW[idx]  = make_float2(W_rel[k * 64 + j],    W_rel[k * 64 + j + 32]);
        sLp[idx] = make_float2(loop_w[k * 64 + j],   loop_w[k * 64 + j + 32]);
        sEv[idx] = make_float2(evolve_w[k * 64 + j], evolve_w[k * 64 + j + 32]);
    }
    __syncthreads();

    const unsigned long long* sWu  = (const unsigned long long*)sW;
    const unsigned long long* sLpu = (const unsigned long long*)sLp;
    const unsigned long long* sEvu = (const unsigned long long*)sEv;

    int lane = tid & 31;
    int warpsPerBlock = blockDim.x >> 5;
    int gwarp = blockIdx.x * warpsPerBlock + (tid >> 5);
    int totalWarps = gridDim.x * warpsPerBlock;
    int ngroups = (N + NPW - 1) / NPW;

    float lw0 = lin_w[lane],      lw1 = lin_w[lane + 32];
    float lw2 = lin_w[64 + lane], lw3 = lin_w[96 + lane];

    for (int g = gwarp; g < ngroups; g += totalWarps) {
        int n0 = g * NPW;
        float f0[NPW], f1[NPW];
        #pragma unroll
        for (int j = 0; j < NPW; j++) {
            int n = n0 + j;
            if (n < N) {
                f0[j] = feat[n * 64 + lane];
                f1[j] = feat[n * 64 + lane + 32];
            } else { f0[j] = 0.f; f1[j] = 0.f; }
        }

        float as[NPW], ad[NPW];
        #pragma unroll
        for (int j = 0; j < NPW; j++) {
            as[j] = f0[j] * lw0 + f1[j] * lw1;
            ad[j] = f0[j] * lw2 + f1[j] * lw3;
        }
        #pragma unroll
        for (int o = 16; o; o >>= 1) {
            #pragma unroll
            for (int j = 0; j < NPW; j++) {
                as[j] += __shfl_xor_sync(0xffffffffu, as[j], o);
                ad[j] += __shfl_xor_sync(0xffffffffu, ad[j], o);
            }
        }
        if (lane == 0) {
            #pragma unroll
            for (int j = 0; j < NPW; j++) {
                int n = n0 + j;
                if (n < N) { g_ssrc[n] = as[j]; g_sdst[n] = ad[j]; }
            }
        }

        unsigned long long p[NPW], lp[NPW], le[NPW];
        #pragma unroll
        for (int j = 0; j < NPW; j++) { p[j] = 0ULL; lp[j] = 0ULL; le[j] = 0ULL; }

        #pragma unroll
        for (int k = 0; k < 32; k++) {
            unsigned long long w  = sWu[k * 32 + lane];
            unsigned long long wl = sLpu[k * 32 + lane];
            unsigned long long we = sEvu[k * 32 + lane];
            #pragma unroll
            for (int j = 0; j < NPW; j++) {
                unsigned long long fk2 = pack2(__shfl_sync(0xffffffffu, f0[j], k));
                ffma2(p[j], fk2, w);
                ffma2(lp[j], fk2, wl);
                ffma2(le[j], fk2, we);
            }
        }
        #pragma unroll
        for (int k = 0; k < 32; k++) {
            unsigned long long w  = sWu[(k + 32) * 32 + lane];
            unsigned long long wl = sLpu[(k + 32) * 32 + lane];
            unsigned long long we = sEvu[(k + 32) * 32 + lane];
            #pragma unroll
            for (int j = 0; j < NPW; j++) {
                unsigned long long fk2 = pack2(__shfl_sync(0xffffffffu, f1[j], k));
                ffma2(p[j], fk2, w);
                ffma2(lp[j], fk2, wl);
                ffma2(le[j], fk2, we);
            }
        }

        #pragma unroll
        for (int j = 0; j < NPW; j++) {
            int n = n0 + j;
            if (n < N) {
                union { unsigned long long u; float2 f; } cp, cl, ce;
                cp.u = p[j]; cl.u = lp[j]; ce.u = le[j];
                g_P[n * 64 + lane]      = cp.f.x;
                g_P[n * 64 + lane + 32] = cp.f.y;
                float2 L = (g_cnt[n] > 0) ? cl.f : ce.f;
                g_L[n * 64 + lane]      = L.x;
                g_L[n * 64 + lane + 32] = L.y;
            }
        }
    }
}

// ---------------------------------------------------------------------------
// Kernel 3: exclusive prefix sum of g_cnt -> g_off, g_cur. Single block.
// Each thread sums a contiguous chunk; Hillis-Steele scan over 1024 partials.
// ---------------------------------------------------------------------------
__global__ void k_scan(int N) {
    __shared__ int ssum[1024];
    int t = threadIdx.x;
    int chunk = (N + 1023) / 1024;
    int start = t * chunk;
    int end = min(start + chunk, N);
    int s = 0;
    for (int i = start; i < end; i++) s += g_cnt[i];
    ssum[t] = s;
    __syncthreads();
    for (int off = 1; off < 1024; off <<= 1) {
        int v = (t >= off) ? ssum[t - off] : 0;
        __syncthreads();
        ssum[t] += v;
        __syncthreads();
    }
    int running = (t == 0) ? 0 : ssum[t - 1];
    for (int i = start; i < end; i++) {
        g_off[i] = running;
        g_cur[i] = running;
        running += g_cnt[i];
    }
}

// ---------------------------------------------------------------------------
// Kernel 4: compute attention + scatter (src, att) into dst-grouped order.
// ---------------------------------------------------------------------------
__global__ void k_scatter(const int* __restrict__ src,
                          const int* __restrict__ dst,
                          const float* __restrict__ lin_b,
                          int E) {
    int e = blockIdx.x * blockDim.x + threadIdx.x;
    if (e >= E) return;
    int s = __ldg(src + e);
    int d = __ldg(dst + e);
    float a = sigrelu(g_ssrc[s] + g_sdst[d] + __ldg(lin_b));
    int pos = atomicAdd(&g_cur[d], 1);
    g_psrc[pos] = s;
    g_patt[pos] = a;
}

// ---------------------------------------------------------------------------
// Kernel 5: warp-per-node gather-reduce + fused finalize.
//   out[n] = tanh((deg>0 ? sum_e att*P[src_e] : feat[n]) * norm[n] + L[n])
// 16 lanes per edge (float4 slots), two halves -> 2 edges concurrent,
// unroll 2 -> 4 P-row gathers in flight per warp. No atomics, one write.
// ---------------------------------------------------------------------------
__global__ void k_reduce(const float* __restrict__ feat,
                         const float* __restrict__ norm,
                         float* __restrict__ out,
                         int N) {
    int warp = (blockIdx.x * blockDim.x + threadIdx.x) >> 5;
    if (warp >= N) return;
    int lane = threadIdx.x & 31;
    int half = lane >> 4;
    int l = lane & 15;
    int n = warp;
    int deg = g_cnt[n];

    float4 acc = make_float4(0.f, 0.f, 0.f, 0.f);
    if (deg > 0) {
        int base = g_off[n];
        int i = half;
        for (; i + 2 < deg; i += 4) {
            int   s0 = g_psrc[base + i];
            float a0 = g_patt[base + i];
            int   s1 = g_psrc[base + i + 2];
            float a1 = g_patt[base + i + 2];
            float4 p0 = ((const float4*)g_P)[s0 * 16 + l];
            float4 p1 = ((const float4*)g_P)[s1 * 16 + l];
            acc.x += a0 * p0.x + a1 * p1.x;
            acc.y += a0 * p0.y + a1 * p1.y;
            acc.z += a0 * p0.z + a1 * p1.z;
            acc.w += a0 * p0.w + a1 * p1.w;
        }
        for (; i < deg; i += 2) {
            int   s0 = g_psrc[base + i];
            float a0 = g_patt[base + i];
            float4 p0 = ((const float4*)g_P)[s0 * 16 + l];
            acc.x += a0 * p0.x;
            acc.y += a0 * p0.y;
            acc.z += a0 * p0.z;
            acc.w += a0 * p0.w;
        }
        // combine the two halves
        acc.x += __shfl_xor_sync(0xffffffffu, acc.x, 16);
        acc.y += __shfl_xor_sync(0xffffffffu, acc.y, 16);
        acc.z += __shfl_xor_sync(0xffffffffu, acc.z, 16);
        acc.w += __shfl_xor_sync(0xffffffffu, acc.w, 16);
    } else if (half == 0) {
        acc = ((const float4*)feat)[n * 16 + l];
    }

    if (half == 0) {
        float nm = norm[n];
        float4 L = ((const float4*)g_L)[n * 16 + l];
        float4 o;
        o.x = tanhf(acc.x * nm + L.x);
        o.y = tanhf(acc.y * nm + L.y);
        o.z = tanhf(acc.z * nm + L.z);
        o.w = tanhf(acc.w * nm + L.w);
        ((float4*)out)[n * 16 + l] = o;
    }
}

// ---------------------------------------------------------------------------
extern "C" void kernel_launch(void* const* d_in, const int* in_sizes, int n_in,
                              void* d_out, int out_size) {
    const float* feat   = (const float*)d_in[0];
    const float* norm   = (const float*)d_in[1];
    const int*   esrc   = (const int*)d_in[2];
    const int*   edst   = (const int*)d_in[3];
    /* d_in[4] = etype : unused (no-op permutation in reference) */
    const float* W_rel  = (const float*)d_in[5];
    const float* lin_w  = (const float*)d_in[6];
    const float* lin_b  = (const float*)d_in[7];
    const float* loop_w = (const float*)d_in[8];
    const float* evolve = (const float*)d_in[9];

    int N = in_sizes[1];   // norm: [N]
    int E = in_sizes[2];   // edge_src: [E]

    k_zero<<<(N + 255) / 256, 256>>>(N);
    k_hist<<<((E + 3) / 4 + 255) / 256, 256>>>(edst, E);
    k_node<<<592, 256>>>(feat, W_rel, lin_w, loop_w, evolve, N);
    k_scan<<<1, 1024>>>(N);
    k_scatter<<<(E + 255) / 256, 256>>>(esrc, edst, lin_b, E);
    {
        long long threads = (long long)N * 32;
        int grid = (int)((threads + 255) / 256);
        k_reduce<<<grid, 256>>>(feat, norm, (float*)d_out, N);
    }
}

// round 13
// speedup vs baseline: 1.5980x; 1.5980x over previous
#include <cuda_runtime.h>

#define MAXN 50000
#define MAXE 1600000
#define DD 64
#define NPW 4   // nodes per warp in k_node

__device__ __align__(16) float g_P[MAXN * DD];     // feat @ W_rel
__device__ __align__(16) float g_L[MAXN * DD];     // feat @ (loop or evolve)
__device__ float g_ssrc[MAXN];
__device__ float g_sdst[MAXN];
__device__ int   g_cnt[MAXN];                      // in-degree
__device__ int   g_off[MAXN];                      // segment base (disjoint, any order)
__device__ int   g_cur[MAXN];                      // scatter cursor
__device__ int   g_total;                          // global segment allocator
__device__ __align__(16) int2 g_pair[MAXE];        // (src, att-bits) grouped by dst

// packed f32x2 FMA: acc = a*b + acc (both lanes)
__device__ __forceinline__ void ffma2(unsigned long long& acc,
                                      unsigned long long a,
                                      unsigned long long b) {
    asm("fma.rn.f32x2 %0, %1, %2, %0;" : "+l"(acc) : "l"(a), "l"(b));
}
__device__ __forceinline__ unsigned long long pack2(float v) {
    unsigned long long r;
    unsigned int u = __float_as_uint(v);
    asm("mov.b64 %0, {%1, %1};" : "=l"(r) : "r"(u));
    return r;
}

__device__ __forceinline__ float sigrelu(float x) {
    return (x > 0.f) ? __fdividef(1.f, 1.f + __expf(-x)) : 0.5f;
}

// ---------------------------------------------------------------------------
// Kernel 0: zero the degree histogram + allocator
// ---------------------------------------------------------------------------
__global__ void k_zero(int N) {
    int i = blockIdx.x * blockDim.x + threadIdx.x;
    if (i < N) g_cnt[i] = 0;
    if (i == 0) g_total = 0;
}

// ---------------------------------------------------------------------------
// Kernel 1: in-degree histogram (4 edges/thread, int4)
// ---------------------------------------------------------------------------
__global__ void k_hist(const int* __restrict__ dst, int E) {
    int i = blockIdx.x * blockDim.x + threadIdx.x;
    int e = i * 4;
    if (e + 3 < E) {
        int4 d = *(const int4*)(dst + e);
        atomicAdd(&g_cnt[d.x], 1);
        atomicAdd(&g_cnt[d.y], 1);
        atomicAdd(&g_cnt[d.z], 1);
        atomicAdd(&g_cnt[d.w], 1);
    } else {
        for (int k = e; k < E; k++) atomicAdd(&g_cnt[dst[k]], 1);
    }
}

// ---------------------------------------------------------------------------
// Kernel 2: node precompute, persistent grid, 4 nodes/warp, packed f32x2 FMA.
//   P = feat@W_rel ; L = feat@(cnt>0 ? loop : evolve) ; ssrc/sdst scalars
// ---------------------------------------------------------------------------
__global__ void k_node(const float* __restrict__ feat,
                       const float* __restrict__ W_rel,
                       const float* __restrict__ lin_w,
                       const float* __restrict__ loop_w,
                       const float* __restrict__ evolve_w,
                       int N) {
    __shared__ float2 sW[2048];
    __shared__ float2 sLp[2048];
    __shared__ float2 sEv[2048];
    int tid = threadIdx.x;
    for (int idx = tid; idx < 2048; idx += blockDim.x) {
        int k = idx >> 5, j = idx & 31;
        sW[idx]  = make_float2(W_rel[k * 64 + j],    W_rel[k * 64 + j + 32]);
        sLp[idx] = make_float2(loop_w[k * 64 + j],   loop_w[k * 64 + j + 32]);
        sEv[idx] = make_float2(evolve_w[k * 64 + j], evolve_w[k * 64 + j + 32]);
    }
    __syncthreads();

    const unsigned long long* sWu  = (const unsigned long long*)sW;
    const unsigned long long* sLpu = (const unsigned long long*)sLp;
    const unsigned long long* sEvu = (const unsigned long long*)sEv;

    int lane = tid & 31;
    int warpsPerBlock = blockDim.x >> 5;
    int gwarp = blockIdx.x * warpsPerBlock + (tid >> 5);
    int totalWarps = gridDim.x * warpsPerBlock;
    int ngroups = (N + NPW - 1) / NPW;

    float lw0 = lin_w[lane],      lw1 = lin_w[lane + 32];
    float lw2 = lin_w[64 + lane], lw3 = lin_w[96 + lane];

    for (int g = gwarp; g < ngroups; g += totalWarps) {
        int n0 = g * NPW;
        float f0[NPW], f1[NPW];
        #pragma unroll
        for (int j = 0; j < NPW; j++) {
            int n = n0 + j;
            if (n < N) {
                f0[j] = feat[n * 64 + lane];
                f1[j] = feat[n * 64 + lane + 32];
            } else { f0[j] = 0.f; f1[j] = 0.f; }
        }

        float as[NPW], ad[NPW];
        #pragma unroll
        for (int j = 0; j < NPW; j++) {
            as[j] = f0[j] * lw0 + f1[j] * lw1;
            ad[j] = f0[j] * lw2 + f1[j] * lw3;
        }
        #pragma unroll
        for (int o = 16; o; o >>= 1) {
            #pragma unroll
            for (int j = 0; j < NPW; j++) {
                as[j] += __shfl_xor_sync(0xffffffffu, as[j], o);
                ad[j] += __shfl_xor_sync(0xffffffffu, ad[j], o);
            }
        }
        if (lane == 0) {
            #pragma unroll
            for (int j = 0; j < NPW; j++) {
                int n = n0 + j;
                if (n < N) { g_ssrc[n] = as[j]; g_sdst[n] = ad[j]; }
            }
        }

        unsigned long long p[NPW], lp[NPW], le[NPW];
        #pragma unroll
        for (int j = 0; j < NPW; j++) { p[j] = 0ULL; lp[j] = 0ULL; le[j] = 0ULL; }

        #pragma unroll
        for (int k = 0; k < 32; k++) {
            unsigned long long w  = sWu[k * 32 + lane];
            unsigned long long wl = sLpu[k * 32 + lane];
            unsigned long long we = sEvu[k * 32 + lane];
            #pragma unroll
            for (int j = 0; j < NPW; j++) {
                unsigned long long fk2 = pack2(__shfl_sync(0xffffffffu, f0[j], k));
                ffma2(p[j], fk2, w);
                ffma2(lp[j], fk2, wl);
                ffma2(le[j], fk2, we);
            }
        }
        #pragma unroll
        for (int k = 0; k < 32; k++) {
            unsigned long long w  = sWu[(k + 32) * 32 + lane];
            unsigned long long wl = sLpu[(k + 32) * 32 + lane];
            unsigned long long we = sEvu[(k + 32) * 32 + lane];
            #pragma unroll
            for (int j = 0; j < NPW; j++) {
                unsigned long long fk2 = pack2(__shfl_sync(0xffffffffu, f1[j], k));
                ffma2(p[j], fk2, w);
                ffma2(lp[j], fk2, wl);
                ffma2(le[j], fk2, we);
            }
        }

        #pragma unroll
        for (int j = 0; j < NPW; j++) {
            int n = n0 + j;
            if (n < N) {
                union { unsigned long long u; float2 f; } cp, cl, ce;
                cp.u = p[j]; cl.u = lp[j]; ce.u = le[j];
                g_P[n * 64 + lane]      = cp.f.x;
                g_P[n * 64 + lane + 32] = cp.f.y;
                float2 L = (g_cnt[n] > 0) ? cl.f : ce.f;
                g_L[n * 64 + lane]      = L.x;
                g_L[n * 64 + lane + 32] = L.y;
            }
        }
    }
}

// ---------------------------------------------------------------------------
// Kernel 3: segment allocation. k_reduce only needs DISJOINT per-node ranges,
// not node-ordered ones — so replace the serial prefix sum with a warp-
// aggregated atomic allocator: warp-scan of 32 counts, one atomicAdd of the
// warp total on a global cursor, broadcast base. 1563 atomics, fully parallel.
// ---------------------------------------------------------------------------
__global__ void k_offsets(int N) {
    int i = blockIdx.x * blockDim.x + threadIdx.x;
    int lane = threadIdx.x & 31;
    int c = (i < N) ? g_cnt[i] : 0;
    // inclusive warp scan of c
    int s = c;
    #pragma unroll
    for (int o = 1; o < 32; o <<= 1) {
        int v = __shfl_up_sync(0xffffffffu, s, o);
        if (lane >= o) s += v;
    }
    int total = __shfl_sync(0xffffffffu, s, 31);
    int base = 0;
    if (lane == 31) base = atomicAdd(&g_total, total);
    base = __shfl_sync(0xffffffffu, base, 31);
    if (i < N) {
        int off = base + s - c;   // exclusive within warp
        g_off[i] = off;
        g_cur[i] = off;
    }
}

// ---------------------------------------------------------------------------
// Kernel 4: compute attention + scatter packed (src, att) into dst-grouped
// order. One 8B store per edge instead of two 4B stores.
// ---------------------------------------------------------------------------
__global__ void k_scatter(const int* __restrict__ src,
                          const int* __restrict__ dst,
                          const float* __restrict__ lin_b,
                          int E) {
    int e = blockIdx.x * blockDim.x + threadIdx.x;
    if (e >= E) return;
    int s = __ldg(src + e);
    int d = __ldg(dst + e);
    float a = sigrelu(g_ssrc[s] + g_sdst[d] + __ldg(lin_b));
    int pos = atomicAdd(&g_cur[d], 1);
    g_pair[pos] = make_int2(s, __float_as_int(a));
}

// ---------------------------------------------------------------------------
// Kernel 5: warp-per-node gather-reduce + fused finalize.
//   out[n] = tanh((deg>0 ? sum_e att*P[src_e] : feat[n]) * norm[n] + L[n])
// 16 lanes per edge (float4 slots), two halves -> 2 edges concurrent,
// unroll 2 -> 4 P-row gathers in flight per warp. No atomics, one write.
// ---------------------------------------------------------------------------
__global__ void k_reduce(const float* __restrict__ feat,
                         const float* __restrict__ norm,
                         float* __restrict__ out,
                         int N) {
    int warp = (blockIdx.x * blockDim.x + threadIdx.x) >> 5;
    if (warp >= N) return;
    int lane = threadIdx.x & 31;
    int half = lane >> 4;
    int l = lane & 15;
    int n = warp;
    int deg = g_cnt[n];

    float4 acc = make_float4(0.f, 0.f, 0.f, 0.f);
    if (deg > 0) {
        int base = g_off[n];
        int i = half;
        for (; i + 2 < deg; i += 4) {
            int2  e0 = g_pair[base + i];
            int2  e1 = g_pair[base + i + 2];
            float a0 = __int_as_float(e0.y);
            float a1 = __int_as_float(e1.y);
            float4 p0 = ((const float4*)g_P)[e0.x * 16 + l];
            float4 p1 = ((const float4*)g_P)[e1.x * 16 + l];
            acc.x += a0 * p0.x + a1 * p1.x;
            acc.y += a0 * p0.y + a1 * p1.y;
            acc.z += a0 * p0.z + a1 * p1.z;
            acc.w += a0 * p0.w + a1 * p1.w;
        }
        for (; i < deg; i += 2) {
            int2  e0 = g_pair[base + i];
            float a0 = __int_as_float(e0.y);
            float4 p0 = ((const float4*)g_P)[e0.x * 16 + l];
            acc.x += a0 * p0.x;
            acc.y += a0 * p0.y;
            acc.z += a0 * p0.z;
            acc.w += a0 * p0.w;
        }
        // combine the two halves
        acc.x += __shfl_xor_sync(0xffffffffu, acc.x, 16);
        acc.y += __shfl_xor_sync(0xffffffffu, acc.y, 16);
        acc.z += __shfl_xor_sync(0xffffffffu, acc.z, 16);
        acc.w += __shfl_xor_sync(0xffffffffu, acc.w, 16);
    } else if (half == 0) {
        acc = ((const float4*)feat)[n * 16 + l];
    }

    if (half == 0) {
        float nm = norm[n];
        float4 L = ((const float4*)g_L)[n * 16 + l];
        float4 o;
        o.x = tanhf(acc.x * nm + L.x);
        o.y = tanhf(acc.y * nm + L.y);
        o.z = tanhf(acc.z * nm + L.z);
        o.w = tanhf(acc.w * nm + L.w);
        ((float4*)out)[n * 16 + l] = o;
    }
}

// ---------------------------------------------------------------------------
extern "C" void kernel_launch(void* const* d_in, const int* in_sizes, int n_in,
                              void* d_out, int out_size) {
    const float* feat   = (const float*)d_in[0];
    const float* norm   = (const float*)d_in[1];
    const int*   esrc   = (const int*)d_in[2];
    const int*   edst   = (const int*)d_in[3];
    /* d_in[4] = etype : unused (no-op permutation in reference) */
    const float* W_rel  = (const float*)d_in[5];
    const float* lin_w  = (const float*)d_in[6];
    const float* lin_b  = (const float*)d_in[7];
    const float* loop_w = (const float*)d_in[8];
    const float* evolve = (const float*)d_in[9];

    int N = in_sizes[1];   // norm: [N]
    int E = in_sizes[2];   // edge_src: [E]

    k_zero<<<(N + 255) / 256, 256>>>(N);
    k_hist<<<((E + 3) / 4 + 255) / 256, 256>>>(edst, E);
    k_node<<<592, 256>>>(feat, W_rel, lin_w, loop_w, evolve, N);
    k_offsets<<<(N + 255) / 256, 256>>>(N);
    k_scatter<<<(E + 255) / 256, 256>>>(esrc, edst, lin_b, E);
    {
        long long threads = (long long)N * 32;
        int grid = (int)((threads + 255) / 256);
        k_reduce<<<grid, 256>>>(feat, norm, (float*)d_out, N);
    }
}

// round 16
// speedup vs baseline: 1.7702x; 1.1077x over previous
#include <cuda_runtime.h>
#include <cuda_fp16.h>

#define MAXN 50000
#define MAXE 1600000
#define DD 64
#define NPW 4   // nodes per warp in k_node

__device__ __align__(16) __half g_Ph[MAXN * DD];   // feat @ W_rel  (fp16)
__device__ __align__(16) float g_L[MAXN * DD];     // feat @ (loop or evolve)
__device__ float g_ssrc[MAXN];
__device__ float g_sdst[MAXN];
__device__ int   g_cnt[MAXN];                      // in-degree
__device__ int   g_off[MAXN];                      // segment base (disjoint)
__device__ int   g_cur[MAXN];                      // scatter cursor
__device__ int   g_total;                          // global segment allocator
__device__ __align__(16) int2 g_pair[MAXE];        // (src, att-bits) grouped by dst

// packed f32x2 FMA: acc = a*b + acc (both lanes)
__device__ __forceinline__ void ffma2(unsigned long long& acc,
                                      unsigned long long a,
                                      unsigned long long b) {
    asm("fma.rn.f32x2 %0, %1, %2, %0;" : "+l"(acc) : "l"(a), "l"(b));
}
__device__ __forceinline__ unsigned long long pack2(float v) {
    unsigned long long r;
    unsigned int u = __float_as_uint(v);
    asm("mov.b64 %0, {%1, %1};" : "=l"(r) : "r"(u));
    return r;
}

__device__ __forceinline__ float sigrelu(float x) {
    return (x > 0.f) ? __fdividef(1.f, 1.f + __expf(-x)) : 0.5f;
}

// ---------------------------------------------------------------------------
// Kernel 0: zero the degree histogram + allocator
// ---------------------------------------------------------------------------
__global__ void k_zero(int N) {
    int i = blockIdx.x * blockDim.x + threadIdx.x;
    if (i < N) g_cnt[i] = 0;
    if (i == 0) g_total = 0;
}

// ---------------------------------------------------------------------------
// Kernel 1: in-degree histogram (4 edges/thread, int4)
// ---------------------------------------------------------------------------
__global__ void k_hist(const int* __restrict__ dst, int E) {
    int i = blockIdx.x * blockDim.x + threadIdx.x;
    int e = i * 4;
    if (e + 3 < E) {
        int4 d = *(const int4*)(dst + e);
        atomicAdd(&g_cnt[d.x], 1);
        atomicAdd(&g_cnt[d.y], 1);
        atomicAdd(&g_cnt[d.z], 1);
        atomicAdd(&g_cnt[d.w], 1);
    } else {
        for (int k = e; k < E; k++) atomicAdd(&g_cnt[dst[k]], 1);
    }
}

// ---------------------------------------------------------------------------
// Kernel 2: node precompute (persistent, 4 nodes/warp, packed f32x2 FMA)
// + segment-allocator prologue folded in (first blocks; hist complete by
// kernel ordering, and k_node completes before k_scatter launches).
// ---------------------------------------------------------------------------
__global__ void k_node(const float* __restrict__ feat,
                       const float* __restrict__ W_rel,
                       const float* __restrict__ lin_w,
                       const float* __restrict__ loop_w,
                       const float* __restrict__ evolve_w,
                       int N) {
    // --- folded k_offsets: warp-aggregated segment allocator ---
    {
        int i = blockIdx.x * blockDim.x + threadIdx.x;
        int lane = threadIdx.x & 31;
        if (i - lane < N) {                       // warp has work
            int c = (i < N) ? g_cnt[i] : 0;
            int s = c;
            #pragma unroll
            for (int o = 1; o < 32; o <<= 1) {
                int v = __shfl_up_sync(0xffffffffu, s, o);
                if (lane >= o) s += v;
            }
            int total = __shfl_sync(0xffffffffu, s, 31);
            int base = 0;
            if (lane == 31 && total > 0) base = atomicAdd(&g_total, total);
            base = __shfl_sync(0xffffffffu, base, 31);
            if (i < N) {
                int off = base + s - c;
                g_off[i] = off;
                g_cur[i] = off;
            }
        }
    }

    __shared__ float2 sW[2048];
    __shared__ float2 sLp[2048];
    __shared__ float2 sEv[2048];
    int tid = threadIdx.x;
    for (int idx = tid; idx < 2048; idx += blockDim.x) {
        int k = idx >> 5, j = idx & 31;
        sW[idx]  = make_float2(W_rel[k * 64 + j],    W_rel[k * 64 + j + 32]);
        sLp[idx] = make_float2(loop_w[k * 64 + j],   loop_w[k * 64 + j + 32]);
        sEv[idx] = make_float2(evolve_w[k * 64 + j], evolve_w[k * 64 + j + 32]);
    }
    __syncthreads();

    const unsigned long long* sWu  = (const unsigned long long*)sW;
    const unsigned long long* sLpu = (const unsigned long long*)sLp;
    const unsigned long long* sEvu = (const unsigned long long*)sEv;

    int lane = tid & 31;
    int warpsPerBlock = blockDim.x >> 5;
    int gwarp = blockIdx.x * warpsPerBlock + (tid >> 5);
    int totalWarps = gridDim.x * warpsPerBlock;
    int ngroups = (N + NPW - 1) / NPW;

    float lw0 = lin_w[lane],      lw1 = lin_w[lane + 32];
    float lw2 = lin_w[64 + lane], lw3 = lin_w[96 + lane];

    for (int g = gwarp; g < ngroups; g += totalWarps) {
        int n0 = g * NPW;
        float f0[NPW], f1[NPW];
        #pragma unroll
        for (int j = 0; j < NPW; j++) {
            int n = n0 + j;
            if (n < N) {
                f0[j] = feat[n * 64 + lane];
                f1[j] = feat[n * 64 + lane + 32];
            } else { f0[j] = 0.f; f1[j] = 0.f; }
        }

        float as[NPW], ad[NPW];
        #pragma unroll
        for (int j = 0; j < NPW; j++) {
            as[j] = f0[j] * lw0 + f1[j] * lw1;
            ad[j] = f0[j] * lw2 + f1[j] * lw3;
        }
        #pragma unroll
        for (int o = 16; o; o >>= 1) {
            #pragma unroll
            for (int j = 0; j < NPW; j++) {
                as[j] += __shfl_xor_sync(0xffffffffu, as[j], o);
                ad[j] += __shfl_xor_sync(0xffffffffu, ad[j], o);
            }
        }
        if (lane == 0) {
            #pragma unroll
            for (int j = 0; j < NPW; j++) {
                int n = n0 + j;
                if (n < N) { g_ssrc[n] = as[j]; g_sdst[n] = ad[j]; }
            }
        }

        unsigned long long p[NPW], lp[NPW], le[NPW];
        #pragma unroll
        for (int j = 0; j < NPW; j++) { p[j] = 0ULL; lp[j] = 0ULL; le[j] = 0ULL; }

        #pragma unroll
        for (int k = 0; k < 32; k++) {
            unsigned long long w  = sWu[k * 32 + lane];
            unsigned long long wl = sLpu[k * 32 + lane];
            unsigned long long we = sEvu[k * 32 + lane];
            #pragma unroll
            for (int j = 0; j < NPW; j++) {
                unsigned long long fk2 = pack2(__shfl_sync(0xffffffffu, f0[j], k));
                ffma2(p[j], fk2, w);
                ffma2(lp[j], fk2, wl);
                ffma2(le[j], fk2, we);
            }
        }
        #pragma unroll
        for (int k = 0; k < 32; k++) {
            unsigned long long w  = sWu[(k + 32) * 32 + lane];
            unsigned long long wl = sLpu[(k + 32) * 32 + lane];
            unsigned long long we = sEvu[(k + 32) * 32 + lane];
            #pragma unroll
            for (int j = 0; j < NPW; j++) {
                unsigned long long fk2 = pack2(__shfl_sync(0xffffffffu, f1[j], k));
                ffma2(p[j], fk2, w);
                ffma2(lp[j], fk2, wl);
                ffma2(le[j], fk2, we);
            }
        }

        #pragma unroll
        for (int j = 0; j < NPW; j++) {
            int n = n0 + j;
            if (n < N) {
                union { unsigned long long u; float2 f; } cp, cl, ce;
                cp.u = p[j]; cl.u = lp[j]; ce.u = le[j];
                // P in fp16 (coalesced: lanes cover contiguous cols)
                g_Ph[n * 64 + lane]      = __float2half(cp.f.x);
                g_Ph[n * 64 + lane + 32] = __float2half(cp.f.y);
                float2 L = (g_cnt[n] > 0) ? cl.f : ce.f;
                g_L[n * 64 + lane]      = L.x;
                g_L[n * 64 + lane + 32] = L.y;
            }
        }
    }
}

// ---------------------------------------------------------------------------
// Kernel 3: compute attention + scatter packed (src, att) into dst-grouped
// order (one 8B store per edge).
// ---------------------------------------------------------------------------
__global__ void k_scatter(const int* __restrict__ src,
                          const int* __restrict__ dst,
                          const float* __restrict__ lin_b,
                          int E) {
    int e = blockIdx.x * blockDim.x + threadIdx.x;
    if (e >= E) return;
    int s = __ldg(src + e);
    int d = __ldg(dst + e);
    float a = sigrelu(g_ssrc[s] + g_sdst[d] + __ldg(lin_b));
    int pos = atomicAdd(&g_cur[d], 1);
    g_pair[pos] = make_int2(s, __float_as_int(a));
}

// ---------------------------------------------------------------------------
// Kernel 4: warp-per-node gather-reduce + fused finalize.
// 8 lanes per edge (each lane: uint4 = 8 fp16 values = 16B of the 128B row),
// 4 edges concurrent per warp, unroll 2 -> 8 gathers in flight.
//   out[n] = tanh((deg>0 ? sum att*P[src] : feat[n]) * norm[n] + L[n])
// ---------------------------------------------------------------------------
__global__ void k_reduce(const float* __restrict__ feat,
                         const float* __restrict__ norm,
                         float* __restrict__ out,
                         int N) {
    int warp = (blockIdx.x * blockDim.x + threadIdx.x) >> 5;
    if (warp >= N) return;
    int lane = threadIdx.x & 31;
    int q = lane >> 3;        // quarter: which of 4 concurrent edges
    int l = lane & 7;         // 16B slot within the 128B fp16 row
    int n = warp;
    int deg = g_cnt[n];

    float acc[8];
    #pragma unroll
    for (int k = 0; k < 8; k++) acc[k] = 0.f;

    if (deg > 0) {
        int base = g_off[n];
        int i = q;
        for (; i + 4 < deg; i += 8) {
            int2 e0 = g_pair[base + i];
            int2 e1 = g_pair[base + i + 4];
            uint4 h0 = ((const uint4*)(g_Ph + e0.x * 64))[l];
            uint4 h1 = ((const uint4*)(g_Ph + e1.x * 64))[l];
            float a0 = __int_as_float(e0.y);
            float a1 = __int_as_float(e1.y);
            const __half2* p0 = (const __half2*)&h0;
            const __half2* p1 = (const __half2*)&h1;
            #pragma unroll
            for (int k = 0; k < 4; k++) {
                float2 v0 = __half22float2(p0[k]);
                float2 v1 = __half22float2(p1[k]);
                acc[2*k]   += a0 * v0.x + a1 * v1.x;
                acc[2*k+1] += a0 * v0.y + a1 * v1.y;
            }
        }
        if (i < deg) {
            int2 e0 = g_pair[base + i];
            uint4 h0 = ((const uint4*)(g_Ph + e0.x * 64))[l];
            float a0 = __int_as_float(e0.y);
            const __half2* p0 = (const __half2*)&h0;
            #pragma unroll
            for (int k = 0; k < 4; k++) {
                float2 v0 = __half22float2(p0[k]);
                acc[2*k]   += a0 * v0.x;
                acc[2*k+1] += a0 * v0.y;
            }
        }
        // combine the 4 quarters (lanes l, l+8, l+16, l+24 hold same slots)
        #pragma unroll
        for (int k = 0; k < 8; k++) {
            acc[k] += __shfl_xor_sync(0xffffffffu, acc[k], 8);
            acc[k] += __shfl_xor_sync(0xffffffffu, acc[k], 16);
        }
    } else if (q == 0) {
        float4 fa = ((const float4*)feat)[n * 16 + l * 2];
        float4 fb = ((const float4*)feat)[n * 16 + l * 2 + 1];
        acc[0] = fa.x; acc[1] = fa.y; acc[2] = fa.z; acc[3] = fa.w;
        acc[4] = fb.x; acc[5] = fb.y; acc[6] = fb.z; acc[7] = fb.w;
    }

    if (q == 0) {   // lanes 0-7: cols l*8 .. l*8+7
        float nm = norm[n];
        float4 L0 = ((const float4*)g_L)[n * 16 + l * 2];
        float4 L1 = ((const float4*)g_L)[n * 16 + l * 2 + 1];
        float4 o0, o1;
        o0.x = tanhf(acc[0] * nm + L0.x);
        o0.y = tanhf(acc[1] * nm + L0.y);
        o0.z = tanhf(acc[2] * nm + L0.z);
        o0.w = tanhf(acc[3] * nm + L0.w);
        o1.x = tanhf(acc[4] * nm + L1.x);
        o1.y = tanhf(acc[5] * nm + L1.y);
        o1.z = tanhf(acc[6] * nm + L1.z);
        o1.w = tanhf(acc[7] * nm + L1.w);
        ((float4*)out)[n * 16 + l * 2]     = o0;
        ((float4*)out)[n * 16 + l * 2 + 1] = o1;
    }
}

// ---------------------------------------------------------------------------
extern "C" void kernel_launch(void* const* d_in, const int* in_sizes, int n_in,
                              void* d_out, int out_size) {
    const float* feat   = (const float*)d_in[0];
    const float* norm   = (const float*)d_in[1];
    const int*   esrc   = (const int*)d_in[2];
    const int*   edst   = (const int*)d_in[3];
    /* d_in[4] = etype : unused (no-op permutation in reference) */
    const float* W_rel  = (const float*)d_in[5];
    const float* lin_w  = (const float*)d_in[6];
    const float* lin_b  = (const float*)d_in[7];
    const float* loop_w = (const float*)d_in[8];
    const float* evolve = (const float*)d_in[9];

    int N = in_sizes[1];   // norm: [N]
    int E = in_sizes[2];   // edge_src: [E]

    k_zero<<<(N + 255) / 256, 256>>>(N);
    k_hist<<<((E + 3) / 4 + 255) / 256, 256>>>(edst, E);
    k_node<<<592, 256>>>(feat, W_rel, lin_w, loop_w, evolve, N);
    k_scatter<<<(E + 255) / 256, 256>>>(esrc, edst, lin_b, E);
    {
        long long threads = (long long)N * 32;
        int grid = (int)((threads + 255) / 256);
        k_reduce<<<grid, 256>>>(feat, norm, (float*)d_out, N);
    }
}